// round 11
// baseline (speedup 1.0000x reference)
#include <cuda_runtime.h>
#include <cuda.h>
#include <cstdint>

// PointPillarScatter on GB300 (sm_103a).
// out[b, c, y, x] = feat[p, c] where idxmap cell == p+1, else 0.
//
// Round 10 -> 11: per-thread STG path replaced by TMA bulk stores.
// Evidence: occ 73->89%, L1 74->53% across rounds with gather time pinned
// at ~92us -> store issue + L1 wavefronts co-limit with DRAM. TMA (UTMASTG)
// eliminates 27.4M STG.128 + all LDS + phase-3 ALU.
//
// Block = one (b, y) row. Two 13.8KB smem buffers [8ch][432x], zeroed ONCE
// (occupied set identical across chunks -> fills overwrite stale values).
// 8 channel-chunks double-buffered via commit_group/wait_group<1>.
// Fallback to the proven R10 gather if the driver entry point is missing.

#define NX_ 432
#define NY_ 496
#define C_  64
#define B_  8
#define NCELLS (B_ * NY_ * NX_)      // 1,714,176
#define CHUNK_C 8                    // channels per TMA store
#define NCHUNKS (C_ / CHUNK_C)       // 8

__device__ __align__(16) int g_idxmap[NCELLS];   // zero-init = all empty

// ---------------------------------------------------------------------------
// Kernel 1: scatter pillar index (p+1), with per-block dtype detection.
// ---------------------------------------------------------------------------
__global__ void scatter_idx_kernel(const void* __restrict__ coords, int P) {
    __shared__ int s_is64;
    if (threadIdx.x < 32) {
        const long long* c64 = (const long long*)coords;
        int rows = P < 64 ? P : 64;
        int ok = 1;
        for (int p = threadIdx.x; p < rows; p += 32) {
            for (int j = 0; j < 4; j++) {
                long long v = c64[4 * p + j];
                if (v < 0 || v >= (1LL << 20)) ok = 0;
            }
        }
        ok = __all_sync(0xFFFFFFFFu, ok);
        if (threadIdx.x == 0) s_is64 = ok;
    }
    __syncthreads();

    int p = blockIdx.x * blockDim.x + threadIdx.x;
    if (p >= P) return;
    int b, z, y, x;
    if (s_is64) {
        const long long* c = (const long long*)coords;
        b = (int)c[4 * p + 0]; z = (int)c[4 * p + 1];
        y = (int)c[4 * p + 2]; x = (int)c[4 * p + 3];
    } else {
        const int* c = (const int*)coords;
        b = c[4 * p + 0]; z = c[4 * p + 1];
        y = c[4 * p + 2]; x = c[4 * p + 3];
    }
    if (b < 0 || b >= B_) return;
    int lin = z + y * NX_ + x;
    if (lin < 0 || lin >= NY_ * NX_) return;
    g_idxmap[b * (NY_ * NX_) + lin] = p + 1;     // 0 stays "empty"
}

// ---------------------------------------------------------------------------
__device__ __forceinline__ uint32_t smem_u32(const void* p) {
    uint32_t a;
    asm("{ .reg .u64 t; cvta.to.shared.u64 t, %1; cvt.u32.u64 %0, t; }"
        : "=r"(a) : "l"(p));
    return a;
}

// ---------------------------------------------------------------------------
// Kernel 2 (TMA path): block = one (b, y) row of 432 cells.
// ---------------------------------------------------------------------------
__global__ __launch_bounds__(256) void gather_tma_kernel(
    const float* __restrict__ feat,
    const __grid_constant__ CUtensorMap tmap)
{
    __shared__ __align__(128) float s_buf[2][CHUNK_C][NX_];  // 2 x 13,824 B
    __shared__ int s_list[NX_];      // (p << 9) | cell
    __shared__ int s_n;

    int tid = threadIdx.x;
    int y = blockIdx.x % NY_;
    int b = blockIdx.x / NY_;

    if (tid == 0) s_n = 0;
    // Zero both buffers ONCE (zeros persist; fills overwrite same cells).
    float4* z = (float4*)&s_buf[0][0][0];
    #pragma unroll 4
    for (int i = tid; i < 2 * CHUNK_C * NX_ / 4; i += 256)
        z[i] = make_float4(0.0f, 0.0f, 0.0f, 0.0f);
    __syncthreads();

    // Phase 1: idxmap read + self-clean + compact occupied cells.
    int cellbase = b * (NY_ * NX_) + y * NX_;
    for (int cell = tid; cell < NX_; cell += 256) {
        int m = g_idxmap[cellbase + cell];
        if (m != 0) {
            g_idxmap[cellbase + cell] = 0;       // restore for next replay
            int pos = atomicAdd(&s_n, 1);
            s_list[pos] = ((m - 1) << 9) | cell; // p, cell packed
        }
    }
    __syncthreads();
    int n_occ = s_n;
    const float4* feat4 = (const float4*)feat;

    for (int chunk = 0; chunk < NCHUNKS; chunk++) {
        float (*buf)[NX_] = s_buf[chunk & 1];
        // Fill occupied cells: 2 float4 (32B) per pillar for this chunk.
        for (int j = tid; j < n_occ * 2; j += 256) {
            int slot = j >> 1;
            int v    = j & 1;
            int e    = s_list[slot];
            int cell = e & 511;
            int p    = e >> 9;
            float4 f = feat4[(size_t)p * 16 + chunk * 2 + v];
            buf[4 * v + 0][cell] = f.x;
            buf[4 * v + 1][cell] = f.y;
            buf[4 * v + 2][cell] = f.z;
            buf[4 * v + 3][cell] = f.w;
        }
        __syncthreads();
        if (tid == 0) {
            asm volatile("fence.proxy.async.shared::cta;" ::: "memory");
            uint32_t saddr = smem_u32(&buf[0][0]);
            int c0 = chunk * CHUNK_C;
            asm volatile(
                "cp.async.bulk.tensor.5d.global.shared::cta.tile.bulk_group "
                "[%0, {%1, %2, %3, %4, %5}], [%6];"
                :: "l"(&tmap), "r"(0), "r"(0), "r"(c0), "r"(y), "r"(b),
                   "r"(saddr)
                : "memory");
            asm volatile("cp.async.bulk.commit_group;" ::: "memory");
            // <=1 group pending -> chunk-1 done -> other buffer free.
            asm volatile("cp.async.bulk.wait_group 1;" ::: "memory");
        }
        __syncthreads();
    }
    if (tid == 0) asm volatile("cp.async.bulk.wait_group 0;" ::: "memory");
}

// ---------------------------------------------------------------------------
// Fallback gather (proven R10 path), used only if driver entry lookup fails.
// ---------------------------------------------------------------------------
#define TILE   108
#define TILES_X (NX_ / TILE)
#define QUADS  (TILE / 4)
#define CGROUPS 10
#define SLOTS  (QUADS * CGROUPS)
#define PITCH  116
#define CH_    32

__global__ __launch_bounds__(256) void gather_fallback_kernel(
    const float* __restrict__ feat, float* __restrict__ out)
{
    __shared__ float s_tile[CH_][PITCH];
    __shared__ __align__(16) int s_idx[PITCH];
    __shared__ int s_list[TILE];
    __shared__ int s_n;

    int bx = blockIdx.x;
    int tx = bx % TILES_X;
    int y  = (bx / TILES_X) % NY_;
    int b  = bx / (TILES_X * NY_);
    int x0 = tx * TILE;
    int tid = threadIdx.x;

    if (tid == 0) s_n = 0;
    if (tid >= TILE && tid < PITCH) s_idx[tid] = -1;
    __syncthreads();

    int cellbase = b * (NY_ * NX_) + y * NX_ + x0;
    if (tid < TILE) {
        int m = g_idxmap[cellbase + tid];
        if (m != 0) g_idxmap[cellbase + tid] = 0;
        s_idx[tid] = m - 1;
        if (m > 0) { int pos = atomicAdd(&s_n, 1); s_list[pos] = tid; }
    }
    __syncthreads();

    int n_occ = s_n;
    const float4* feat4 = (const float4*)feat;
    size_t outbase = (size_t)b * (C_ * NY_ * NX_) + (size_t)y * NX_ + x0;
    const int4* s_idx4 = (const int4*)s_idx;

    #pragma unroll
    for (int half = 0; half < 2; half++) {
        for (int j = tid; j < n_occ * 8; j += 256) {
            int slot = j >> 3, v = j & 7;
            int cell = s_list[slot];
            int p    = s_idx[cell];
            float4 f = feat4[(size_t)p * 16 + half * 8 + v];
            s_tile[4 * v + 0][cell] = f.x;
            s_tile[4 * v + 1][cell] = f.y;
            s_tile[4 * v + 2][cell] = f.z;
            s_tile[4 * v + 3][cell] = f.w;
        }
        __syncthreads();
        const float* outh = out + outbase + (size_t)(half * CH_) * (NY_ * NX_);
        for (int slot = tid; slot < SLOTS; slot += 256) {
            int q = slot % QUADS, c0 = slot / QUADS;
            int4 m = s_idx4[q];
            bool any = (m.x >= 0) | (m.y >= 0) | (m.z >= 0) | (m.w >= 0);
            const float* outq = outh + 4 * q;
            #pragma unroll
            for (int c = 0; c < CH_; c += CGROUPS) {
                int cc = c + c0;
                if (cc >= CH_) break;
                float4 v = make_float4(0.0f, 0.0f, 0.0f, 0.0f);
                if (any) {
                    float4 t = ((const float4*)s_tile[cc])[q];
                    if (m.x >= 0) v.x = t.x;
                    if (m.y >= 0) v.y = t.y;
                    if (m.z >= 0) v.z = t.z;
                    if (m.w >= 0) v.w = t.w;
                }
                __stcs((float4*)(outq + (size_t)cc * (NY_ * NX_)), v);
            }
        }
        if (half == 0) __syncthreads();
    }
}

// ---------------------------------------------------------------------------
typedef CUresult (*EncodeFn)(CUtensorMap*, CUtensorMapDataType, cuuint32_t,
    void*, const cuuint64_t*, const cuuint64_t*, const cuuint32_t*,
    const cuuint32_t*, CUtensorMapInterleave, CUtensorMapSwizzle,
    CUtensorMapL2promotion, CUtensorMapFloatOOBfill);

extern "C" void kernel_launch(void* const* d_in, const int* in_sizes, int n_in,
                              void* d_out, int out_size) {
    const float* feat   = (const float*)d_in[0];
    const void*  coords = d_in[1];
    int P = in_sizes[0] / C_;   // features are [P, 64] f32

    constexpr int TPB = 256;
    scatter_idx_kernel<<<(P + TPB - 1) / TPB, TPB>>>(coords, P);

    // Build the 5D output tensor map: [x_in=216, x_out=2, c, y, b].
    EncodeFn enc = nullptr;
    cudaDriverEntryPointQueryResult qr = cudaDriverEntryPointSymbolNotFound;
    cudaGetDriverEntryPointByVersion("cuTensorMapEncodeTiled", (void**)&enc,
                                     12000, cudaEnableDefault, &qr);
    bool tma_ok = (enc != nullptr) && (qr == cudaDriverEntryPointSuccess);

    CUtensorMap tmap;
    if (tma_ok) {
        cuuint64_t dims[5]    = {216, 2, C_, NY_, B_};
        cuuint64_t strides[4] = {216ull * 4,                       // x_out
                                 (cuuint64_t)NY_ * NX_ * 4,        // c
                                 (cuuint64_t)NX_ * 4,              // y
                                 (cuuint64_t)C_ * NY_ * NX_ * 4};  // b
        cuuint32_t box[5]  = {216, 2, CHUNK_C, 1, 1};
        cuuint32_t estr[5] = {1, 1, 1, 1, 1};
        CUresult r = enc(&tmap, CU_TENSOR_MAP_DATA_TYPE_FLOAT32, 5, d_out,
                         dims, strides, box, estr,
                         CU_TENSOR_MAP_INTERLEAVE_NONE,
                         CU_TENSOR_MAP_SWIZZLE_NONE,
                         CU_TENSOR_MAP_L2_PROMOTION_L2_128B,
                         CU_TENSOR_MAP_FLOAT_OOB_FILL_NONE);
        if (r != CUDA_SUCCESS) tma_ok = false;
    }

    if (tma_ok) {
        gather_tma_kernel<<<B_ * NY_, TPB>>>(feat, tmap);
    } else {
        gather_fallback_kernel<<<B_ * NY_ * TILES_X, TPB>>>(feat, (float*)d_out);
    }
}

// round 12
// speedup vs baseline: 1.0322x; 1.0322x over previous
#include <cuda_runtime.h>
#include <cuda.h>
#include <cstdint>

// PointPillarScatter on GB300 (sm_103a).
// out[b, c, y, x] = feat[p, c] where idxmap cell == p+1, else 0.
//
// Round 11 -> 12: PDL overlap. Scatter (~2-3us) was fully serialized before
// gather, but gather's smem zeroing doesn't depend on it. Gather is launched
// with ProgrammaticStreamSerialization; it zeroes its buffers, THEN
// cudaGridDependencySynchronize()s before reading idxmap. Scatter triggers
// early completion. TMA store path (R11, gather ncu 92->78us) unchanged.

#define NX_ 432
#define NY_ 496
#define C_  64
#define B_  8
#define NCELLS (B_ * NY_ * NX_)      // 1,714,176
#define CHUNK_C 8                    // channels per TMA store
#define NCHUNKS (C_ / CHUNK_C)       // 8

__device__ __align__(16) int g_idxmap[NCELLS];   // zero-init = all empty

// ---------------------------------------------------------------------------
// Kernel 1: scatter pillar index (p+1), with per-block dtype detection.
// ---------------------------------------------------------------------------
__global__ void scatter_idx_kernel(const void* __restrict__ coords, int P) {
    __shared__ int s_is64;
    if (threadIdx.x < 32) {
        const long long* c64 = (const long long*)coords;
        int rows = P < 64 ? P : 64;
        int ok = 1;
        for (int p = threadIdx.x; p < rows; p += 32) {
            for (int j = 0; j < 4; j++) {
                long long v = c64[4 * p + j];
                if (v < 0 || v >= (1LL << 20)) ok = 0;
            }
        }
        ok = __all_sync(0xFFFFFFFFu, ok);
        if (threadIdx.x == 0) s_is64 = ok;
    }
    __syncthreads();

    int p = blockIdx.x * blockDim.x + threadIdx.x;
    if (p < P) {
        int b, z, y, x;
        if (s_is64) {
            const long long* c = (const long long*)coords;
            b = (int)c[4 * p + 0]; z = (int)c[4 * p + 1];
            y = (int)c[4 * p + 2]; x = (int)c[4 * p + 3];
        } else {
            const int* c = (const int*)coords;
            b = c[4 * p + 0]; z = c[4 * p + 1];
            y = c[4 * p + 2]; x = c[4 * p + 3];
        }
        if (b >= 0 && b < B_) {
            int lin = z + y * NX_ + x;
            if (lin >= 0 && lin < NY_ * NX_)
                g_idxmap[b * (NY_ * NX_) + lin] = p + 1;  // 0 stays "empty"
        }
    }
    // Let the dependent gather grid begin launching (it still gridsyncs on
    // our full completion before reading idxmap).
    cudaTriggerProgrammaticLaunchCompletion();
}

// ---------------------------------------------------------------------------
__device__ __forceinline__ uint32_t smem_u32(const void* p) {
    uint32_t a;
    asm("{ .reg .u64 t; cvta.to.shared.u64 t, %1; cvt.u32.u64 %0, t; }"
        : "=r"(a) : "l"(p));
    return a;
}

// ---------------------------------------------------------------------------
// Kernel 2 (TMA path): block = one (b, y) row of 432 cells.
// ---------------------------------------------------------------------------
__global__ __launch_bounds__(256) void gather_tma_kernel(
    const float* __restrict__ feat,
    const __grid_constant__ CUtensorMap tmap)
{
    __shared__ __align__(128) float s_buf[2][CHUNK_C][NX_];  // 2 x 13,824 B
    __shared__ int s_list[NX_];      // (p << 9) | cell
    __shared__ int s_n;

    int tid = threadIdx.x;
    int y = blockIdx.x % NY_;
    int b = blockIdx.x / NY_;

    if (tid == 0) s_n = 0;
    // Zero both buffers ONCE (scatter-independent; overlaps with scatter
    // under PDL). Zeros persist; chunk fills overwrite the same cells.
    float4* z = (float4*)&s_buf[0][0][0];
    #pragma unroll 4
    for (int i = tid; i < 2 * CHUNK_C * NX_ / 4; i += 256)
        z[i] = make_float4(0.0f, 0.0f, 0.0f, 0.0f);

    // Wait for the scatter grid's writes to be visible.
    cudaGridDependencySynchronize();
    __syncthreads();

    // Phase 1: idxmap read + self-clean + compact occupied cells.
    int cellbase = b * (NY_ * NX_) + y * NX_;
    for (int cell = tid; cell < NX_; cell += 256) {
        int m = g_idxmap[cellbase + cell];
        if (m != 0) {
            g_idxmap[cellbase + cell] = 0;       // restore for next replay
            int pos = atomicAdd(&s_n, 1);
            s_list[pos] = ((m - 1) << 9) | cell; // p, cell packed
        }
    }
    __syncthreads();
    int n_occ = s_n;
    const float4* feat4 = (const float4*)feat;

    for (int chunk = 0; chunk < NCHUNKS; chunk++) {
        float (*buf)[NX_] = s_buf[chunk & 1];
        // Fill occupied cells: 2 float4 (32B) per pillar for this chunk.
        for (int j = tid; j < n_occ * 2; j += 256) {
            int slot = j >> 1;
            int v    = j & 1;
            int e    = s_list[slot];
            int cell = e & 511;
            int p    = e >> 9;
            float4 f = feat4[(size_t)p * 16 + chunk * 2 + v];
            buf[4 * v + 0][cell] = f.x;
            buf[4 * v + 1][cell] = f.y;
            buf[4 * v + 2][cell] = f.z;
            buf[4 * v + 3][cell] = f.w;
        }
        __syncthreads();
        if (tid == 0) {
            asm volatile("fence.proxy.async.shared::cta;" ::: "memory");
            uint32_t saddr = smem_u32(&buf[0][0]);
            int c0 = chunk * CHUNK_C;
            asm volatile(
                "cp.async.bulk.tensor.5d.global.shared::cta.tile.bulk_group "
                "[%0, {%1, %2, %3, %4, %5}], [%6];"
                :: "l"(&tmap), "r"(0), "r"(0), "r"(c0), "r"(y), "r"(b),
                   "r"(saddr)
                : "memory");
            asm volatile("cp.async.bulk.commit_group;" ::: "memory");
            // <=1 group pending -> chunk-1 done -> other buffer free.
            asm volatile("cp.async.bulk.wait_group 1;" ::: "memory");
        }
        __syncthreads();
    }
    if (tid == 0) asm volatile("cp.async.bulk.wait_group 0;" ::: "memory");
}

// ---------------------------------------------------------------------------
// Fallback gather (proven R10 path), used only if driver entry lookup fails.
// ---------------------------------------------------------------------------
#define TILE   108
#define TILES_X (NX_ / TILE)
#define QUADS  (TILE / 4)
#define CGROUPS 10
#define SLOTS  (QUADS * CGROUPS)
#define PITCH  116
#define CH_    32

__global__ __launch_bounds__(256) void gather_fallback_kernel(
    const float* __restrict__ feat, float* __restrict__ out)
{
    __shared__ float s_tile[CH_][PITCH];
    __shared__ __align__(16) int s_idx[PITCH];
    __shared__ int s_list[TILE];
    __shared__ int s_n;

    int bx = blockIdx.x;
    int tx = bx % TILES_X;
    int y  = (bx / TILES_X) % NY_;
    int b  = bx / (TILES_X * NY_);
    int x0 = tx * TILE;
    int tid = threadIdx.x;

    if (tid == 0) s_n = 0;
    if (tid >= TILE && tid < PITCH) s_idx[tid] = -1;
    __syncthreads();

    int cellbase = b * (NY_ * NX_) + y * NX_ + x0;
    if (tid < TILE) {
        int m = g_idxmap[cellbase + tid];
        if (m != 0) g_idxmap[cellbase + tid] = 0;
        s_idx[tid] = m - 1;
        if (m > 0) { int pos = atomicAdd(&s_n, 1); s_list[pos] = tid; }
    }
    __syncthreads();

    int n_occ = s_n;
    const float4* feat4 = (const float4*)feat;
    size_t outbase = (size_t)b * (C_ * NY_ * NX_) + (size_t)y * NX_ + x0;
    const int4* s_idx4 = (const int4*)s_idx;

    #pragma unroll
    for (int half = 0; half < 2; half++) {
        for (int j = tid; j < n_occ * 8; j += 256) {
            int slot = j >> 3, v = j & 7;
            int cell = s_list[slot];
            int p    = s_idx[cell];
            float4 f = feat4[(size_t)p * 16 + half * 8 + v];
            s_tile[4 * v + 0][cell] = f.x;
            s_tile[4 * v + 1][cell] = f.y;
            s_tile[4 * v + 2][cell] = f.z;
            s_tile[4 * v + 3][cell] = f.w;
        }
        __syncthreads();
        const float* outh = out + outbase + (size_t)(half * CH_) * (NY_ * NX_);
        for (int slot = tid; slot < SLOTS; slot += 256) {
            int q = slot % QUADS, c0 = slot / QUADS;
            int4 m = s_idx4[q];
            bool any = (m.x >= 0) | (m.y >= 0) | (m.z >= 0) | (m.w >= 0);
            const float* outq = outh + 4 * q;
            #pragma unroll
            for (int c = 0; c < CH_; c += CGROUPS) {
                int cc = c + c0;
                if (cc >= CH_) break;
                float4 v = make_float4(0.0f, 0.0f, 0.0f, 0.0f);
                if (any) {
                    float4 t = ((const float4*)s_tile[cc])[q];
                    if (m.x >= 0) v.x = t.x;
                    if (m.y >= 0) v.y = t.y;
                    if (m.z >= 0) v.z = t.z;
                    if (m.w >= 0) v.w = t.w;
                }
                __stcs((float4*)(outq + (size_t)cc * (NY_ * NX_)), v);
            }
        }
        if (half == 0) __syncthreads();
    }
}

// ---------------------------------------------------------------------------
typedef CUresult (*EncodeFn)(CUtensorMap*, CUtensorMapDataType, cuuint32_t,
    void*, const cuuint64_t*, const cuuint64_t*, const cuuint32_t*,
    const cuuint32_t*, CUtensorMapInterleave, CUtensorMapSwizzle,
    CUtensorMapL2promotion, CUtensorMapFloatOOBfill);

extern "C" void kernel_launch(void* const* d_in, const int* in_sizes, int n_in,
                              void* d_out, int out_size) {
    const float* feat   = (const float*)d_in[0];
    const void*  coords = d_in[1];
    int P = in_sizes[0] / C_;   // features are [P, 64] f32

    constexpr int TPB = 256;
    scatter_idx_kernel<<<(P + TPB - 1) / TPB, TPB>>>(coords, P);

    // Build the 5D output tensor map: [x_in=216, x_out=2, c, y, b].
    EncodeFn enc = nullptr;
    cudaDriverEntryPointQueryResult qr = cudaDriverEntryPointSymbolNotFound;
    cudaGetDriverEntryPointByVersion("cuTensorMapEncodeTiled", (void**)&enc,
                                     12000, cudaEnableDefault, &qr);
    bool tma_ok = (enc != nullptr) && (qr == cudaDriverEntryPointSuccess);

    CUtensorMap tmap;
    if (tma_ok) {
        cuuint64_t dims[5]    = {216, 2, C_, NY_, B_};
        cuuint64_t strides[4] = {216ull * 4,                       // x_out
                                 (cuuint64_t)NY_ * NX_ * 4,        // c
                                 (cuuint64_t)NX_ * 4,              // y
                                 (cuuint64_t)C_ * NY_ * NX_ * 4};  // b
        cuuint32_t box[5]  = {216, 2, CHUNK_C, 1, 1};
        cuuint32_t estr[5] = {1, 1, 1, 1, 1};
        CUresult r = enc(&tmap, CU_TENSOR_MAP_DATA_TYPE_FLOAT32, 5, d_out,
                         dims, strides, box, estr,
                         CU_TENSOR_MAP_INTERLEAVE_NONE,
                         CU_TENSOR_MAP_SWIZZLE_NONE,
                         CU_TENSOR_MAP_L2_PROMOTION_L2_128B,
                         CU_TENSOR_MAP_FLOAT_OOB_FILL_NONE);
        if (r != CUDA_SUCCESS) tma_ok = false;
    }

    if (tma_ok) {
        // PDL launch: overlap gather's zeroing prologue with the scatter.
        cudaLaunchAttribute attr[1];
        attr[0].id = cudaLaunchAttributeProgrammaticStreamSerialization;
        attr[0].val.programmaticStreamSerializationAllowed = 1;
        cudaLaunchConfig_t cfg = {};
        cfg.gridDim  = dim3(B_ * NY_, 1, 1);
        cfg.blockDim = dim3(TPB, 1, 1);
        cfg.attrs    = attr;
        cfg.numAttrs = 1;
        cudaLaunchKernelEx(&cfg, gather_tma_kernel, feat, tmap);
    } else {
        gather_fallback_kernel<<<B_ * NY_ * TILES_X, TPB>>>(feat, (float*)d_out);
    }
}